// round 7
// baseline (speedup 1.0000x reference)
#include <cuda_runtime.h>
#include <cuda_bf16.h>
#include <math.h>
#include <stdint.h>

// ---------------- problem constants ----------------
#define N_NODES   100000
#define N_EDGES   1600000
#define IN_DIM    256
#define OUT_DIM   128
#define NEG_SLOPE 0.2f
#define LAMBDA    0.5f
#define EPS_      1e-8f

// ---------------- device scratch (static, no allocs) ----------------
__device__ float g_h [(size_t)N_NODES * OUT_DIM];
__device__ float g_xw[(size_t)N_NODES * OUT_DIM];
__device__ __nv_bfloat16 g_xhi[(size_t)N_NODES * IN_DIM];
__device__ __nv_bfloat16 g_xlo[(size_t)N_NODES * IN_DIM];
__device__ __nv_bfloat16 g_wghi[OUT_DIM * IN_DIM];
__device__ __nv_bfloat16 g_wglo[OUT_DIM * IN_DIM];
__device__ __nv_bfloat16 g_wfhi[OUT_DIM * IN_DIM];
__device__ __nv_bfloat16 g_wflo[OUT_DIM * IN_DIM];
__device__ float g_asrc[N_NODES];
__device__ float g_adst[N_NODES];
__device__ int   g_deg[N_NODES];
__device__ int   g_off[N_NODES];
__device__ int   g_cursor[N_NODES];
__device__ int   g_csr_src[N_EDGES];
__device__ float g_csr_beta[N_EDGES];
__device__ int   g_is64;

#define SCAN_B 1024
#define NCHUNK ((N_NODES + SCAN_B - 1) / SCAN_B)   // 98
__device__ int g_bsum[NCHUNK];

// ---------------- kernel 0: sniff edge_index dtype ----------------
__global__ void k_sniff(const int* __restrict__ ei_words) {
    if (threadIdx.x == 0 && blockIdx.x == 0) {
        int allzero = 1;
        #pragma unroll 1
        for (int i = 0; i < 64; i++) {
            if (ei_words[2 * i + 1] != 0) { allzero = 0; break; }
        }
        g_is64 = allzero;
    }
}

// ---------------- kernel 1: zero small scratch ----------------
__global__ void k_zero_misc() {
    int i = blockIdx.x * blockDim.x + threadIdx.x;
    if (i < N_NODES) {
        g_deg[i] = 0;
        g_cursor[i] = 0;
        g_asrc[i] = 0.0f;
        g_adst[i] = 0.0f;
    }
}

// ---------------- edge decode helpers ----------------
__device__ __forceinline__ int edge_at(const void* ei, size_t idx) {
    return g_is64 ? (int)((const long long*)ei)[idx]
                  : ((const int*)ei)[idx];
}

// ---------------- kernel: degree histogram ----------------
__global__ void k_hist(const void* __restrict__ ei) {
    int e = blockIdx.x * blockDim.x + threadIdx.x;
    if (e >= N_EDGES) return;
    int d = edge_at(ei, (size_t)N_EDGES + e);
    atomicAdd(&g_deg[d], 1);
}

// ---------------- bf16 split-pack: float4 -> hi uint2 + lo uint2 ----------
__device__ __forceinline__ uint2 split_pack4(float4 v, uint2& lo_out) {
    float2 p0 = make_float2(v.x, v.y);
    float2 p1 = make_float2(v.z, v.w);
    __nv_bfloat162 h0 = __float22bfloat162_rn(p0);
    __nv_bfloat162 h1 = __float22bfloat162_rn(p1);
    float2 b0 = __bfloat1622float2(h0);
    float2 b1 = __bfloat1622float2(h1);
    __nv_bfloat162 l0 = __float22bfloat162_rn(make_float2(p0.x - b0.x, p0.y - b0.y));
    __nv_bfloat162 l1 = __float22bfloat162_rn(make_float2(p1.x - b1.x, p1.y - b1.y));
    lo_out = make_uint2(*(uint32_t*)&l0, *(uint32_t*)&l1);
    return make_uint2(*(uint32_t*)&h0, *(uint32_t*)&h1);
}

// ---------------- kernel: split X into hi/lo bf16 ----------------
__global__ __launch_bounds__(256)
void k_split_x(const float* __restrict__ X) {
    size_t idx = (size_t)blockIdx.x * blockDim.x + threadIdx.x;  // float4 index
    if (idx >= (size_t)N_NODES * (IN_DIM / 4)) return;
    float4 v = *(const float4*)(X + idx * 4);
    uint2 lo;
    uint2 hi = split_pack4(v, lo);
    *(uint2*)(g_xhi + idx * 4) = hi;
    *(uint2*)(g_xlo + idx * 4) = lo;
}

// ---------------- kernel: split both weight matrices ----------------
__global__ __launch_bounds__(256)
void k_split_w(const float* __restrict__ Wg, const float* __restrict__ Wf) {
    int idx = blockIdx.x * blockDim.x + threadIdx.x;   // float4 index, 2 mats
    const int per_mat = OUT_DIM * IN_DIM / 4;          // 8192
    if (idx >= 2 * per_mat) return;
    const float* W = (idx < per_mat) ? Wg : Wf;
    __nv_bfloat16* Hi = (idx < per_mat) ? g_wghi : g_wfhi;
    __nv_bfloat16* Lo = (idx < per_mat) ? g_wglo : g_wflo;
    int i = (idx < per_mat) ? idx : idx - per_mat;
    float4 v = *(const float4*)(W + (size_t)i * 4);
    uint2 lo;
    uint2 hi = split_pack4(v, lo);
    *(uint2*)(Hi + (size_t)i * 4) = hi;
    *(uint2*)(Lo + (size_t)i * 4) = lo;
}

// ---------------- mma + cp.async helpers ----------------
__device__ __forceinline__ void mma_bf16(float* d, const uint32_t* a,
                                         uint32_t b0, uint32_t b1) {
    asm volatile(
        "mma.sync.aligned.m16n8k16.row.col.f32.bf16.bf16.f32 "
        "{%0,%1,%2,%3}, {%4,%5,%6,%7}, {%8,%9}, {%0,%1,%2,%3};\n"
        : "+f"(d[0]), "+f"(d[1]), "+f"(d[2]), "+f"(d[3])
        : "r"(a[0]), "r"(a[1]), "r"(a[2]), "r"(a[3]), "r"(b0), "r"(b1));
}

__device__ __forceinline__ void cp16(uint32_t sdst, const void* gsrc) {
    asm volatile("cp.async.ca.shared.global [%0], [%1], 16;\n"
                 :: "r"(sdst), "l"(gsrc));
}
__device__ __forceinline__ void cp_commit() {
    asm volatile("cp.async.commit_group;\n");
}
template <int N>
__device__ __forceinline__ void cp_wait() {
    asm volatile("cp.async.wait_group %0;\n" :: "n"(N));
}

// ---------------- kernel: dual GEMM, pre-split bf16, double-buffered -------
// CTA tile 128x128, BK=32, 2 stages, 8 warps (4M x 2N), warp tile 32x64.
// PADK=40 (80B rows): fragment bank = (20*gid + tig + kk/2) mod 32 -> all
// 32 lanes distinct, conflict-free. 80 % 16 == 0 keeps cp.async 16B-aligned.
#define GBM 128
#define GBK 32
#define PADK 40
#define BUF_E (GBM * PADK)                 // 5120 bf16 per buffer
#define STAGE_E (4 * BUF_E)                // Ahi|Alo|Bhi|Blo
#define SMEM_GEMM (2 * STAGE_E * (int)sizeof(__nv_bfloat16))   // 81920 bytes

__global__ __launch_bounds__(256, 2)
void k_gemm_tc(const float* __restrict__ att_s,
               const float* __restrict__ att_d) {
    extern __shared__ __nv_bfloat16 smem[];
    const uint32_t sbase = (uint32_t)__cvta_generic_to_shared(smem);

    const int is_h = (blockIdx.y == 0);
    const __nv_bfloat16* Whi = is_h ? g_wghi : g_wfhi;
    const __nv_bfloat16* Wlo = is_h ? g_wglo : g_wflo;
    float* C = is_h ? g_h : g_xw;

    const int row0 = blockIdx.x * GBM;
    const int tid  = threadIdx.x;
    const int warp = tid >> 5, lane = tid & 31;
    const int wm = warp & 3;
    const int wn = warp >> 2;
    const int gid = lane >> 2;
    const int tig = lane & 3;

    // per-thread fill coordinates: 512 chunks per buffer, 2 per thread
    const int ch0_row = tid >> 2, ch0_c = (tid & 3) * 8;            // chunk tid
    const int ch1_row = (tid + 256) >> 2, ch1_c = ((tid + 256) & 3) * 8;
    const int ga0 = min(row0 + ch0_row, N_NODES - 1);
    const int ga1 = min(row0 + ch1_row, N_NODES - 1);

    auto fill = [&](int st, int k0) {
        uint32_t s = sbase + (uint32_t)(st * STAGE_E) * 2;
        // A hi/lo
        cp16(s + (ch0_row * PADK + ch0_c) * 2,
             g_xhi + (size_t)ga0 * IN_DIM + k0 + ch0_c);
        cp16(s + (ch1_row * PADK + ch1_c) * 2,
             g_xhi + (size_t)ga1 * IN_DIM + k0 + ch1_c);
        cp16(s + (BUF_E + ch0_row * PADK + ch0_c) * 2,
             g_xlo + (size_t)ga0 * IN_DIM + k0 + ch0_c);
        cp16(s + (BUF_E + ch1_row * PADK + ch1_c) * 2,
             g_xlo + (size_t)ga1 * IN_DIM + k0 + ch1_c);
        // B hi/lo (128 weight rows, always valid)
        cp16(s + (2 * BUF_E + ch0_row * PADK + ch0_c) * 2,
             Whi + (size_t)ch0_row * IN_DIM + k0 + ch0_c);
        cp16(s + (2 * BUF_E + ch1_row * PADK + ch1_c) * 2,
             Whi + (size_t)ch1_row * IN_DIM + k0 + ch1_c);
        cp16(s + (3 * BUF_E + ch0_row * PADK + ch0_c) * 2,
             Wlo + (size_t)ch0_row * IN_DIM + k0 + ch0_c);
        cp16(s + (3 * BUF_E + ch1_row * PADK + ch1_c) * 2,
             Wlo + (size_t)ch1_row * IN_DIM + k0 + ch1_c);
        cp_commit();
    };

    float acc[2][8][4];
    #pragma unroll
    for (int mi = 0; mi < 2; mi++)
        #pragma unroll
        for (int ni = 0; ni < 8; ni++)
            #pragma unroll
            for (int j = 0; j < 4; j++) acc[mi][ni][j] = 0.0f;

    const int NSTAGES = IN_DIM / GBK;   // 8
    fill(0, 0);

    #pragma unroll 1
    for (int s = 0; s < NSTAGES; s++) {
        if (s + 1 < NSTAGES) fill((s + 1) & 1, (s + 1) * GBK);
        if (s + 1 < NSTAGES) cp_wait<1>(); else cp_wait<0>();
        __syncthreads();

        const __nv_bfloat16* stage = smem + (s & 1) * STAGE_E;
        const __nv_bfloat16 (*Ahi)[PADK] = (const __nv_bfloat16(*)[PADK])(stage);
        const __nv_bfloat16 (*Alo)[PADK] = (const __nv_bfloat16(*)[PADK])(stage + BUF_E);
        const __nv_bfloat16 (*Bhi)[PADK] = (const __nv_bfloat16(*)[PADK])(stage + 2 * BUF_E);
        const __nv_bfloat16 (*Blo)[PADK] = (const __nv_bfloat16(*)[PADK])(stage + 3 * BUF_E);

        #pragma unroll
        for (int ks = 0; ks < 2; ks++) {
            const int kk = ks * 16;
            uint32_t ah[2][4], al[2][4];
            #pragma unroll
            for (int mi = 0; mi < 2; mi++) {
                int r = wm * 32 + mi * 16 + gid;
                ah[mi][0] = *(const uint32_t*)&Ahi[r    ][kk + 2*tig    ];
                ah[mi][1] = *(const uint32_t*)&Ahi[r + 8][kk + 2*tig    ];
                ah[mi][2] = *(const uint32_t*)&Ahi[r    ][kk + 2*tig + 8];
                ah[mi][3] = *(const uint32_t*)&Ahi[r + 8][kk + 2*tig + 8];
                al[mi][0] = *(const uint32_t*)&Alo[r    ][kk + 2*tig    ];
                al[mi][1] = *(const uint32_t*)&Alo[r + 8][kk + 2*tig    ];
                al[mi][2] = *(const uint32_t*)&Alo[r    ][kk + 2*tig + 8];
                al[mi][3] = *(const uint32_t*)&Alo[r + 8][kk + 2*tig + 8];
            }
            #pragma unroll
            for (int ni = 0; ni < 8; ni++) {
                int n = wn * 64 + ni * 8 + gid;
                uint32_t bh0 = *(const uint32_t*)&Bhi[n][kk + 2*tig    ];
                uint32_t bh1 = *(const uint32_t*)&Bhi[n][kk + 2*tig + 8];
                uint32_t bl0 = *(const uint32_t*)&Blo[n][kk + 2*tig    ];
                uint32_t bl1 = *(const uint32_t*)&Blo[n][kk + 2*tig + 8];
                #pragma unroll
                for (int mi = 0; mi < 2; mi++) {
                    mma_bf16(acc[mi][ni], ah[mi], bh0, bh1);   // hi*hi
                    mma_bf16(acc[mi][ni], al[mi], bh0, bh1);   // lo*hi
                    mma_bf16(acc[mi][ni], ah[mi], bl0, bl1);   // hi*lo
                }
            }
        }
        __syncthreads();
    }

    // ---- epilogue: store C ----
    #pragma unroll
    for (int mi = 0; mi < 2; mi++) {
        #pragma unroll
        for (int ni = 0; ni < 8; ni++) {
            int col = wn * 64 + ni * 8 + 2 * tig;
            int r0  = row0 + wm * 32 + mi * 16 + gid;
            if (r0 < N_NODES)
                *(float2*)(C + (size_t)r0 * OUT_DIM + col) =
                    make_float2(acc[mi][ni][0], acc[mi][ni][1]);
            int r1 = r0 + 8;
            if (r1 < N_NODES)
                *(float2*)(C + (size_t)r1 * OUT_DIM + col) =
                    make_float2(acc[mi][ni][2], acc[mi][ni][3]);
        }
    }

    // ---- fused attention dots (h branch only) ----
    if (is_h) {
        #pragma unroll
        for (int mi = 0; mi < 2; mi++) {
            float s0 = 0.f, d0 = 0.f, s1 = 0.f, d1 = 0.f;
            #pragma unroll
            for (int ni = 0; ni < 8; ni++) {
                int col = wn * 64 + ni * 8 + 2 * tig;
                float a0 = __ldg(att_s + col), a1 = __ldg(att_s + col + 1);
                float b0 = __ldg(att_d + col), b1 = __ldg(att_d + col + 1);
                s0 += acc[mi][ni][0] * a0 + acc[mi][ni][1] * a1;
                d0 += acc[mi][ni][0] * b0 + acc[mi][ni][1] * b1;
                s1 += acc[mi][ni][2] * a0 + acc[mi][ni][3] * a1;
                d1 += acc[mi][ni][2] * b0 + acc[mi][ni][3] * b1;
            }
            #pragma unroll
            for (int o = 1; o <= 2; o <<= 1) {
                s0 += __shfl_xor_sync(0xffffffffu, s0, o);
                d0 += __shfl_xor_sync(0xffffffffu, d0, o);
                s1 += __shfl_xor_sync(0xffffffffu, s1, o);
                d1 += __shfl_xor_sync(0xffffffffu, d1, o);
            }
            if (tig == 0) {
                int r0 = row0 + wm * 32 + mi * 16 + gid;
                if (r0 < N_NODES) {
                    atomicAdd(&g_asrc[r0], s0);
                    atomicAdd(&g_adst[r0], d0);
                }
                int r1 = r0 + 8;
                if (r1 < N_NODES) {
                    atomicAdd(&g_asrc[r1], s1);
                    atomicAdd(&g_adst[r1], d1);
                }
            }
        }
    }
}

// ---------------- scan kernels ----------------
__global__ void k_scan1() {
    __shared__ int sh[SCAN_B];
    int i = blockIdx.x * SCAN_B + threadIdx.x;
    int v = (i < N_NODES) ? g_deg[i] : 0;
    sh[threadIdx.x] = v;
    __syncthreads();
    for (int o = 1; o < SCAN_B; o <<= 1) {
        int t = (threadIdx.x >= o) ? sh[threadIdx.x - o] : 0;
        __syncthreads();
        sh[threadIdx.x] += t;
        __syncthreads();
    }
    if (i < N_NODES) g_off[i] = sh[threadIdx.x] - v;
    if (threadIdx.x == SCAN_B - 1) g_bsum[blockIdx.x] = sh[threadIdx.x];
}

__global__ void k_scan2() {
    __shared__ int sh[128];
    int v = (threadIdx.x < NCHUNK) ? g_bsum[threadIdx.x] : 0;
    sh[threadIdx.x] = v;
    __syncthreads();
    for (int o = 1; o < 128; o <<= 1) {
        int t = (threadIdx.x >= o) ? sh[threadIdx.x - o] : 0;
        __syncthreads();
        sh[threadIdx.x] += t;
        __syncthreads();
    }
    if (threadIdx.x < NCHUNK) g_bsum[threadIdx.x] = sh[threadIdx.x] - v;
}

__global__ void k_scan3() {
    int i = blockIdx.x * SCAN_B + threadIdx.x;
    if (i < N_NODES) g_off[i] += g_bsum[blockIdx.x];
}

// ---------------- kernel: scatter edges into CSR ----------------
__global__ void k_scatter(const void* __restrict__ ei,
                          const float* __restrict__ beta) {
    int e = blockIdx.x * blockDim.x + threadIdx.x;
    if (e >= N_EDGES) return;
    int s = edge_at(ei, e);
    int d = edge_at(ei, (size_t)N_EDGES + e);
    int pos = g_off[d] + atomicAdd(&g_cursor[d], 1);
    g_csr_src[pos]  = s;
    g_csr_beta[pos] = beta[e];
}

// ---------------- kernel: warp-per-node fused aggregation ----------------
__global__ __launch_bounds__(256)
void k_agg(const float* __restrict__ bias, float* __restrict__ out) {
    int node = (blockIdx.x * blockDim.x + threadIdx.x) >> 5;
    if (node >= N_NODES) return;
    int lane = threadIdx.x & 31;

    int beg = g_off[node];
    int deg = g_deg[node];
    float adst = g_adst[node];

    float psum = 0.0f;
    for (int i = beg + lane; i < beg + deg; i += 32) {
        int s = g_csr_src[i];
        float xv = g_asrc[s] + adst;
        if (xv < 0.0f) xv *= NEG_SLOPE;
        psum += 1.0f / (1.0f + expf(-xv));
    }
    #pragma unroll
    for (int o = 16; o; o >>= 1) psum += __shfl_xor_sync(0xffffffffu, psum, o);
    float invden = LAMBDA / (psum + EPS_);

    float4 acc = make_float4(0.f, 0.f, 0.f, 0.f);
    #pragma unroll 2
    for (int i = beg; i < beg + deg; i++) {
        int s   = g_csr_src[i];
        float b = g_csr_beta[i];
        float xv = g_asrc[s] + adst;
        if (xv < 0.0f) xv *= NEG_SLOPE;
        float al = 1.0f / (1.0f + expf(-xv));
        float cA = al * invden;
        float cB = (1.0f - LAMBDA) * b;
        float4 h4 = __ldg((const float4*)(g_h  + (size_t)s * OUT_DIM) + lane);
        float4 x4 = __ldg((const float4*)(g_xw + (size_t)s * OUT_DIM) + lane);
        acc.x += cA * h4.x + cB * x4.x;
        acc.y += cA * h4.y + cB * x4.y;
        acc.z += cA * h4.z + cB * x4.z;
        acc.w += cA * h4.w + cB * x4.w;
    }

    float4 bv = *(const float4*)(bias + lane * 4);
    float4 v;
    v.x = acc.x + LAMBDA * bv.x;
    v.y = acc.y + LAMBDA * bv.y;
    v.z = acc.z + LAMBDA * bv.z;
    v.w = acc.w + LAMBDA * bv.w;
    v.x = (v.x > 0.0f) ? v.x : expm1f(v.x);
    v.y = (v.y > 0.0f) ? v.y : expm1f(v.y);
    v.z = (v.z > 0.0f) ? v.z : expm1f(v.z);
    v.w = (v.w > 0.0f) ? v.w : expm1f(v.w);
    *(float4*)(out + (size_t)node * OUT_DIM + lane * 4) = v;
}

// ---------------- launch ----------------
extern "C" void kernel_launch(void* const* d_in, const int* in_sizes, int n_in,
                              void* d_out, int out_size) {
    const float* x       = (const float*)d_in[0];
    const void*  ei      = d_in[1];
    const float* beta    = (const float*)d_in[2];
    const float* W_gat   = (const float*)d_in[3];
    const float* att_src = (const float*)d_in[4];
    const float* att_dst = (const float*)d_in[5];
    const float* bias    = (const float*)d_in[6];
    const float* W_fixed = (const float*)d_in[7];
    float* out = (float*)d_out;

    static cudaStream_t s2 = nullptr;
    static cudaEvent_t evFork = nullptr, evJoin = nullptr;
    static int init_done = 0;
    if (!init_done) {
        cudaFuncSetAttribute(k_gemm_tc,
                             cudaFuncAttributeMaxDynamicSharedMemorySize,
                             SMEM_GEMM);
        cudaStreamCreateWithFlags(&s2, cudaStreamNonBlocking);
        cudaEventCreateWithFlags(&evFork, cudaEventDisableTiming);
        cudaEventCreateWithFlags(&evJoin, cudaEventDisableTiming);
        init_done = 1;
    }

    // prologue on main stream
    k_zero_misc<<<(N_NODES + 255) / 256, 256>>>();

    // ---- fork: CSR build on s2, split+GEMM on main ----
    cudaEventRecord(evFork, 0);
    cudaStreamWaitEvent(s2, evFork, 0);

    // main stream: split pre-pass then GEMM
    k_split_w<<<(2 * OUT_DIM * IN_DIM / 4 + 255) / 256, 256>>>(W_gat, W_fixed);
    {
        size_t n4 = (size_t)N_NODES * (IN_DIM / 4);
        k_split_x<<<(int)((n4 + 255) / 256), 256>>>(x);
    }
    {
        dim3 grid((N_NODES + GBM - 1) / GBM, 2);
        k_gemm_tc<<<grid, 256, SMEM_GEMM>>>(att_src, att_dst);
    }

    // side stream: CSR build
    k_sniff<<<1, 32, 0, s2>>>((const int*)ei);
    k_hist<<<(N_EDGES + 255) / 256, 256, 0, s2>>>(ei);
    k_scan1<<<NCHUNK, SCAN_B, 0, s2>>>();
    k_scan2<<<1, 128, 0, s2>>>();
    k_scan3<<<NCHUNK, SCAN_B, 0, s2>>>();
    k_scatter<<<(N_EDGES + 255) / 256, 256, 0, s2>>>(ei, beta);

    // ---- join ----
    cudaEventRecord(evJoin, s2);
    cudaStreamWaitEvent(0, evJoin, 0);

    // fused aggregation + bias + ELU
    k_agg<<<(N_NODES * 32 + 255) / 256, 256>>>(bias, out);
}

// round 8
// speedup vs baseline: 1.0971x; 1.0971x over previous
#include <cuda_runtime.h>
#include <cuda_bf16.h>
#include <math.h>
#include <stdint.h>

// ---------------- problem constants ----------------
#define N_NODES   100000
#define N_EDGES   1600000
#define IN_DIM    256
#define OUT_DIM   128
#define NEG_SLOPE 0.2f
#define LAMBDA    0.5f
#define EPS_      1e-8f

// ---------------- device scratch (static, no allocs) ----------------
__device__ float g_h [(size_t)N_NODES * OUT_DIM];   // x @ W_gat^T
__device__ float g_xw[(size_t)N_NODES * OUT_DIM];   // x @ W_fixed^T
__device__ float g_asrc[N_NODES];
__device__ float g_adst[N_NODES];
__device__ int   g_deg[N_NODES];
__device__ int   g_off[N_NODES];
__device__ int   g_cursor[N_NODES];
__device__ int   g_csr_src[N_EDGES];
__device__ float g_csr_beta[N_EDGES];
__device__ int   g_is64;

#define SCAN_B 1024
#define NCHUNK ((N_NODES + SCAN_B - 1) / SCAN_B)   // 98
__device__ int g_bsum[NCHUNK];

// ---------------- kernel 0: sniff edge_index dtype ----------------
__global__ void k_sniff(const int* __restrict__ ei_words) {
    if (threadIdx.x == 0 && blockIdx.x == 0) {
        int allzero = 1;
        #pragma unroll 1
        for (int i = 0; i < 64; i++) {
            if (ei_words[2 * i + 1] != 0) { allzero = 0; break; }
        }
        g_is64 = allzero;
    }
}

// ---------------- kernel 1: zero small scratch ----------------
__global__ void k_zero_misc() {
    int i = blockIdx.x * blockDim.x + threadIdx.x;
    if (i < N_NODES) {
        g_deg[i] = 0;
        g_cursor[i] = 0;
        g_asrc[i] = 0.0f;
        g_adst[i] = 0.0f;
    }
}

// ---------------- edge decode helpers ----------------
__device__ __forceinline__ int edge_at(const void* ei, size_t idx) {
    return g_is64 ? (int)((const long long*)ei)[idx]
                  : ((const int*)ei)[idx];
}

// ---------------- kernel: degree histogram ----------------
__global__ void k_hist(const void* __restrict__ ei) {
    int e = blockIdx.x * blockDim.x + threadIdx.x;
    if (e >= N_EDGES) return;
    int d = edge_at(ei, (size_t)N_EDGES + e);
    atomicAdd(&g_deg[d], 1);
}

// ---------------- bf16 split-pack: float4 -> hi uint2 + lo uint2 ----------
__device__ __forceinline__ uint2 split_pack4(float4 v, uint2& lo_out) {
    float2 p0 = make_float2(v.x, v.y);
    float2 p1 = make_float2(v.z, v.w);
    __nv_bfloat162 h0 = __float22bfloat162_rn(p0);
    __nv_bfloat162 h1 = __float22bfloat162_rn(p1);
    float2 b0 = __bfloat1622float2(h0);
    float2 b1 = __bfloat1622float2(h1);
    __nv_bfloat162 l0 = __float22bfloat162_rn(make_float2(p0.x - b0.x, p0.y - b0.y));
    __nv_bfloat162 l1 = __float22bfloat162_rn(make_float2(p1.x - b1.x, p1.y - b1.y));
    lo_out = make_uint2(*(uint32_t*)&l0, *(uint32_t*)&l1);
    return make_uint2(*(uint32_t*)&h0, *(uint32_t*)&h1);
}

__device__ __forceinline__ void mma_bf16(float* d, const uint32_t* a,
                                         uint32_t b0, uint32_t b1) {
    asm volatile(
        "mma.sync.aligned.m16n8k16.row.col.f32.bf16.bf16.f32 "
        "{%0,%1,%2,%3}, {%4,%5,%6,%7}, {%8,%9}, {%0,%1,%2,%3};\n"
        : "+f"(d[0]), "+f"(d[1]), "+f"(d[2]), "+f"(d[3])
        : "r"(a[0]), "r"(a[1]), "r"(a[2]), "r"(a[3]), "r"(b0), "r"(b1));
}

__device__ __forceinline__ void ldsm_x4(uint32_t& r0, uint32_t& r1,
                                        uint32_t& r2, uint32_t& r3,
                                        uint32_t addr) {
    asm volatile("ldmatrix.sync.aligned.m8n8.x4.shared.b16 {%0,%1,%2,%3}, [%4];"
                 : "=r"(r0), "=r"(r1), "=r"(r2), "=r"(r3) : "r"(addr));
}

// ---------------- kernel: dual GEMM on tensor cores (bf16x3 + ldmatrix) ----
// C[m][n] = sum_k X[m][k]*W[n][k] via 3-term bf16 split (hh + lh + hl).
// CTA tile 128x128, BK=64, 8 warps (4M x 2N), warp tile 32x64.
// PADK=72 (144B rows): LDSM phases hit 4 distinct bank quads -> conflict-free.
#define GBM 128
#define GBK 64
#define PADK 72
#define BUF_E (GBM * PADK)                                       // 9216 bf16
#define SMEM_GEMM (4 * BUF_E * (int)sizeof(__nv_bfloat16))       // 73728 bytes

__global__ __launch_bounds__(256, 2)
void k_gemm_tc(const float* __restrict__ X,
               const float* __restrict__ Wg,
               const float* __restrict__ Wf,
               const float* __restrict__ att_s,
               const float* __restrict__ att_d) {
    extern __shared__ __nv_bfloat16 smem[];
    __nv_bfloat16 (*Ahi)[PADK] = (__nv_bfloat16(*)[PADK])(smem);
    __nv_bfloat16 (*Alo)[PADK] = (__nv_bfloat16(*)[PADK])(smem + 1 * BUF_E);
    __nv_bfloat16 (*Bhi)[PADK] = (__nv_bfloat16(*)[PADK])(smem + 2 * BUF_E);
    __nv_bfloat16 (*Blo)[PADK] = (__nv_bfloat16(*)[PADK])(smem + 3 * BUF_E);
    const uint32_t sbase = (uint32_t)__cvta_generic_to_shared(smem);

    const float* W = (blockIdx.y == 0) ? Wg : Wf;
    float*       C = (blockIdx.y == 0) ? g_h : g_xw;

    const int row0 = blockIdx.x * GBM;
    const int tid  = threadIdx.x;
    const int warp = tid >> 5, lane = tid & 31;
    const int wm = warp & 3;      // 0..3 -> 32-row slice
    const int wn = warp >> 2;     // 0..1 -> 64-col slice
    const int gid = lane >> 2;    // 0..7
    const int tig = lane & 3;     // 0..3

    // ldmatrix lane address components
    const int laneA_row = lane & 15;            // row within 16-row block
    const int laneA_col = (lane >> 4) * 8;      // 0 or 8 (k tile column)
    const int laneB_grp = (lane >> 4) * 8;      // 0 or 8 (n group)
    const int laneB_row = lane & 7;
    const int laneB_col = ((lane >> 3) & 1) * 8;

    // per-warp LDSM base addresses (bytes), kk added at use time
    uint32_t aAhi[2], aAlo[2], aBhi[4], aBlo[4];
    #pragma unroll
    for (int mi = 0; mi < 2; mi++) {
        int r = wm * 32 + mi * 16 + laneA_row;
        aAhi[mi] = sbase + (uint32_t)((0 * BUF_E + r * PADK + laneA_col) * 2);
        aAlo[mi] = sbase + (uint32_t)((1 * BUF_E + r * PADK + laneA_col) * 2);
    }
    #pragma unroll
    for (int nh = 0; nh < 4; nh++) {
        int n = wn * 64 + nh * 16 + laneB_grp + laneB_row;
        aBhi[nh] = sbase + (uint32_t)((2 * BUF_E + n * PADK + laneB_col) * 2);
        aBlo[nh] = sbase + (uint32_t)((3 * BUF_E + n * PADK + laneB_col) * 2);
    }

    float acc[2][8][4];
    #pragma unroll
    for (int mi = 0; mi < 2; mi++)
        #pragma unroll
        for (int ni = 0; ni < 8; ni++)
            #pragma unroll
            for (int j = 0; j < 4; j++) acc[mi][ni][j] = 0.0f;

    for (int k0 = 0; k0 < IN_DIM; k0 += GBK) {
        // ---- fill A tile (128 rows x 64 k): 2048 float4 / 256 thr = 8 each
        #pragma unroll
        for (int i = 0; i < 8; i++) {
            int idx = tid + i * 256;          // 0..2047
            int m   = idx >> 4;               // 0..127
            int k4  = (idx & 15) << 2;        // 0,4,..,60
            float4 v = make_float4(0.f, 0.f, 0.f, 0.f);
            if (row0 + m < N_NODES)
                v = *(const float4*)(X + (size_t)(row0 + m) * IN_DIM + k0 + k4);
            uint2 lo;
            uint2 hi = split_pack4(v, lo);
            *(uint2*)&Ahi[m][k4] = hi;
            *(uint2*)&Alo[m][k4] = lo;
        }
        // ---- fill B tile (128 n-rows x 64 k)
        #pragma unroll
        for (int i = 0; i < 8; i++) {
            int idx = tid + i * 256;
            int n   = idx >> 4;
            int k4  = (idx & 15) << 2;
            float4 v = *(const float4*)(W + (size_t)n * IN_DIM + k0 + k4);
            uint2 lo;
            uint2 hi = split_pack4(v, lo);
            *(uint2*)&Bhi[n][k4] = hi;
            *(uint2*)&Blo[n][k4] = lo;
        }
        __syncthreads();

        #pragma unroll
        for (int ks = 0; ks < 4; ks++) {
            const uint32_t koff = (uint32_t)(ks * 16 * 2);   // kk bytes
            // A fragments via 4 LDSM.x4
            uint32_t ah[2][4], al[2][4];
            #pragma unroll
            for (int mi = 0; mi < 2; mi++) {
                ldsm_x4(ah[mi][0], ah[mi][1], ah[mi][2], ah[mi][3], aAhi[mi] + koff);
                ldsm_x4(al[mi][0], al[mi][1], al[mi][2], al[mi][3], aAlo[mi] + koff);
            }
            // B in nh pairs: 2 LDSM.x4 + 12 MMAs each
            #pragma unroll
            for (int nh = 0; nh < 4; nh++) {
                uint32_t bh[4], bl[4];
                ldsm_x4(bh[0], bh[1], bh[2], bh[3], aBhi[nh] + koff);
                ldsm_x4(bl[0], bl[1], bl[2], bl[3], aBlo[nh] + koff);
                #pragma unroll
                for (int half = 0; half < 2; half++) {
                    int ni = nh * 2 + half;
                    uint32_t bh0 = bh[half * 2], bh1 = bh[half * 2 + 1];
                    uint32_t bl0 = bl[half * 2], bl1 = bl[half * 2 + 1];
                    #pragma unroll
                    for (int mi = 0; mi < 2; mi++) {
                        mma_bf16(acc[mi][ni], ah[mi], bh0, bh1);   // hi*hi
                        mma_bf16(acc[mi][ni], al[mi], bh0, bh1);   // lo*hi
                        mma_bf16(acc[mi][ni], ah[mi], bl0, bl1);   // hi*lo
                    }
                }
            }
        }
        __syncthreads();
    }

    // ---- epilogue: store C ----
    #pragma unroll
    for (int mi = 0; mi < 2; mi++) {
        #pragma unroll
        for (int ni = 0; ni < 8; ni++) {
            int col = wn * 64 + ni * 8 + 2 * tig;
            int r0  = row0 + wm * 32 + mi * 16 + gid;
            if (r0 < N_NODES)
                *(float2*)(C + (size_t)r0 * OUT_DIM + col) =
                    make_float2(acc[mi][ni][0], acc[mi][ni][1]);
            int r1 = r0 + 8;
            if (r1 < N_NODES)
                *(float2*)(C + (size_t)r1 * OUT_DIM + col) =
                    make_float2(acc[mi][ni][2], acc[mi][ni][3]);
        }
    }

    // ---- fused attention dots (h branch only) ----
    if (blockIdx.y == 0) {
        #pragma unroll
        for (int mi = 0; mi < 2; mi++) {
            float s0 = 0.f, d0 = 0.f, s1 = 0.f, d1 = 0.f;
            #pragma unroll
            for (int ni = 0; ni < 8; ni++) {
                int col = wn * 64 + ni * 8 + 2 * tig;
                float a0 = __ldg(att_s + col), a1 = __ldg(att_s + col + 1);
                float b0 = __ldg(att_d + col), b1 = __ldg(att_d + col + 1);
                s0 += acc[mi][ni][0] * a0 + acc[mi][ni][1] * a1;
                d0 += acc[mi][ni][0] * b0 + acc[mi][ni][1] * b1;
                s1 += acc[mi][ni][2] * a0 + acc[mi][ni][3] * a1;
                d1 += acc[mi][ni][2] * b0 + acc[mi][ni][3] * b1;
            }
            #pragma unroll
            for (int o = 1; o <= 2; o <<= 1) {
                s0 += __shfl_xor_sync(0xffffffffu, s0, o);
                d0 += __shfl_xor_sync(0xffffffffu, d0, o);
                s1 += __shfl_xor_sync(0xffffffffu, s1, o);
                d1 += __shfl_xor_sync(0xffffffffu, d1, o);
            }
            if (tig == 0) {
                int r0 = row0 + wm * 32 + mi * 16 + gid;
                if (r0 < N_NODES) {
                    atomicAdd(&g_asrc[r0], s0);
                    atomicAdd(&g_adst[r0], d0);
                }
                int r1 = r0 + 8;
                if (r1 < N_NODES) {
                    atomicAdd(&g_asrc[r1], s1);
                    atomicAdd(&g_adst[r1], d1);
                }
            }
        }
    }
}

// ---------------- scan kernels ----------------
__global__ void k_scan1() {
    __shared__ int sh[SCAN_B];
    int i = blockIdx.x * SCAN_B + threadIdx.x;
    int v = (i < N_NODES) ? g_deg[i] : 0;
    sh[threadIdx.x] = v;
    __syncthreads();
    for (int o = 1; o < SCAN_B; o <<= 1) {
        int t = (threadIdx.x >= o) ? sh[threadIdx.x - o] : 0;
        __syncthreads();
        sh[threadIdx.x] += t;
        __syncthreads();
    }
    if (i < N_NODES) g_off[i] = sh[threadIdx.x] - v;
    if (threadIdx.x == SCAN_B - 1) g_bsum[blockIdx.x] = sh[threadIdx.x];
}

__global__ void k_scan2() {
    __shared__ int sh[128];
    int v = (threadIdx.x < NCHUNK) ? g_bsum[threadIdx.x] : 0;
    sh[threadIdx.x] = v;
    __syncthreads();
    for (int o = 1; o < 128; o <<= 1) {
        int t = (threadIdx.x >= o) ? sh[threadIdx.x - o] : 0;
        __syncthreads();
        sh[threadIdx.x] += t;
        __syncthreads();
    }
    if (threadIdx.x < NCHUNK) g_bsum[threadIdx.x] = sh[threadIdx.x] - v;
}

__global__ void k_scan3() {
    int i = blockIdx.x * SCAN_B + threadIdx.x;
    if (i < N_NODES) g_off[i] += g_bsum[blockIdx.x];
}

// ---------------- kernel: scatter edges into CSR ----------------
__global__ void k_scatter(const void* __restrict__ ei,
                          const float* __restrict__ beta) {
    int e = blockIdx.x * blockDim.x + threadIdx.x;
    if (e >= N_EDGES) return;
    int s = edge_at(ei, e);
    int d = edge_at(ei, (size_t)N_EDGES + e);
    int pos = g_off[d] + atomicAdd(&g_cursor[d], 1);
    g_csr_src[pos]  = s;
    g_csr_beta[pos] = beta[e];
}

// ---------------- kernel: warp-per-node fused aggregation ----------------
__global__ __launch_bounds__(256)
void k_agg(const float* __restrict__ bias, float* __restrict__ out) {
    int node = (blockIdx.x * blockDim.x + threadIdx.x) >> 5;
    if (node >= N_NODES) return;
    int lane = threadIdx.x & 31;

    int beg = g_off[node];
    int deg = g_deg[node];
    float adst = g_adst[node];

    float psum = 0.0f;
    for (int i = beg + lane; i < beg + deg; i += 32) {
        int s = g_csr_src[i];
        float xv = g_asrc[s] + adst;
        if (xv < 0.0f) xv *= NEG_SLOPE;
        psum += 1.0f / (1.0f + expf(-xv));
    }
    #pragma unroll
    for (int o = 16; o; o >>= 1) psum += __shfl_xor_sync(0xffffffffu, psum, o);
    float invden = LAMBDA / (psum + EPS_);

    float4 acc = make_float4(0.f, 0.f, 0.f, 0.f);
    #pragma unroll 2
    for (int i = beg; i < beg + deg; i++) {
        int s   = g_csr_src[i];
        float b = g_csr_beta[i];
        float xv = g_asrc[s] + adst;
        if (xv < 0.0f) xv *= NEG_SLOPE;
        float al = 1.0f / (1.0f + expf(-xv));
        float cA = al * invden;
        float cB = (1.0f - LAMBDA) * b;
        float4 h4 = __ldg((const float4*)(g_h  + (size_t)s * OUT_DIM) + lane);
        float4 x4 = __ldg((const float4*)(g_xw + (size_t)s * OUT_DIM) + lane);
        acc.x += cA * h4.x + cB * x4.x;
        acc.y += cA * h4.y + cB * x4.y;
        acc.z += cA * h4.z + cB * x4.z;
        acc.w += cA * h4.w + cB * x4.w;
    }

    float4 bv = *(const float4*)(bias + lane * 4);
    float4 v;
    v.x = acc.x + LAMBDA * bv.x;
    v.y = acc.y + LAMBDA * bv.y;
    v.z = acc.z + LAMBDA * bv.z;
    v.w = acc.w + LAMBDA * bv.w;
    v.x = (v.x > 0.0f) ? v.x : expm1f(v.x);
    v.y = (v.y > 0.0f) ? v.y : expm1f(v.y);
    v.z = (v.z > 0.0f) ? v.z : expm1f(v.z);
    v.w = (v.w > 0.0f) ? v.w : expm1f(v.w);
    *(float4*)(out + (size_t)node * OUT_DIM + lane * 4) = v;
}

// ---------------- launch ----------------
extern "C" void kernel_launch(void* const* d_in, const int* in_sizes, int n_in,
                              void* d_out, int out_size) {
    const float* x       = (const float*)d_in[0];
    const void*  ei      = d_in[1];
    const float* beta    = (const float*)d_in[2];
    const float* W_gat   = (const float*)d_in[3];
    const float* att_src = (const float*)d_in[4];
    const float* att_dst = (const float*)d_in[5];
    const float* bias    = (const float*)d_in[6];
    const float* W_fixed = (const float*)d_in[7];
    float* out = (float*)d_out;

    static cudaStream_t s2 = nullptr;
    static cudaEvent_t evFork = nullptr, evJoin = nullptr;
    static int init_done = 0;
    if (!init_done) {
        cudaFuncSetAttribute(k_gemm_tc,
                             cudaFuncAttributeMaxDynamicSharedMemorySize,
                             SMEM_GEMM);
        cudaStreamCreateWithFlags(&s2, cudaStreamNonBlocking);
        cudaEventCreateWithFlags(&evFork, cudaEventDisableTiming);
        cudaEventCreateWithFlags(&evJoin, cudaEventDisableTiming);
        init_done = 1;
    }

    // prologue on main stream: zero scratch used by both branches
    k_zero_misc<<<(N_NODES + 255) / 256, 256>>>();

    // ---- fork: CSR build on s2, GEMM on main ----
    cudaEventRecord(evFork, 0);
    cudaStreamWaitEvent(s2, evFork, 0);

    {   // dual GEMM + fused attention dots (main stream)
        dim3 grid((N_NODES + GBM - 1) / GBM, 2);
        k_gemm_tc<<<grid, 256, SMEM_GEMM>>>(x, W_gat, W_fixed, att_src, att_dst);
    }

    // side stream: CSR build
    k_sniff<<<1, 32, 0, s2>>>((const int*)ei);
    k_hist<<<(N_EDGES + 255) / 256, 256, 0, s2>>>(ei);
    k_scan1<<<NCHUNK, SCAN_B, 0, s2>>>();
    k_scan2<<<1, 128, 0, s2>>>();
    k_scan3<<<NCHUNK, SCAN_B, 0, s2>>>();
    k_scatter<<<(N_EDGES + 255) / 256, 256, 0, s2>>>(ei, beta);

    // ---- join ----
    cudaEventRecord(evJoin, s2);
    cudaStreamWaitEvent(0, evJoin, 0);

    // fused aggregation + bias + ELU
    k_agg<<<(N_NODES * 32 + 255) / 256, 256>>>(bias, out);
}

// round 9
// speedup vs baseline: 1.1949x; 1.0892x over previous
#include <cuda_runtime.h>
#include <cuda_bf16.h>
#include <math.h>
#include <stdint.h>

// ---------------- problem constants ----------------
#define N_NODES   100000
#define N_EDGES   1600000
#define IN_DIM    256
#define OUT_DIM   128
#define NEG_SLOPE 0.2f
#define LAMBDA    0.5f
#define EPS_      1e-8f

// ---------------- device scratch (static, no allocs) ----------------
// g_hx: interleaved [node][0:128)=h, [128:256)=xw  (1KB per node)
__device__ float g_hx[(size_t)N_NODES * 2 * OUT_DIM];
__device__ float g_asrc[N_NODES];
__device__ float g_adst[N_NODES];
__device__ int   g_deg[N_NODES];
__device__ int   g_off[N_NODES];
__device__ int   g_cursor[N_NODES];
__device__ int   g_csr_src[N_EDGES];
__device__ float g_csr_beta[N_EDGES];
__device__ int   g_is64;

#define SCAN_B 1024
#define NCHUNK ((N_NODES + SCAN_B - 1) / SCAN_B)   // 98
__device__ int g_bsum[NCHUNK];

// ---------------- kernel 0: sniff edge_index dtype ----------------
__global__ void k_sniff(const int* __restrict__ ei_words) {
    if (threadIdx.x == 0 && blockIdx.x == 0) {
        int allzero = 1;
        #pragma unroll 1
        for (int i = 0; i < 64; i++) {
            if (ei_words[2 * i + 1] != 0) { allzero = 0; break; }
        }
        g_is64 = allzero;
    }
}

// ---------------- kernel 1: zero small scratch ----------------
__global__ void k_zero_misc() {
    int i = blockIdx.x * blockDim.x + threadIdx.x;
    if (i < N_NODES) {
        g_deg[i] = 0;
        g_cursor[i] = 0;
        g_asrc[i] = 0.0f;
        g_adst[i] = 0.0f;
    }
}

// ---------------- edge decode helpers ----------------
__device__ __forceinline__ int edge_at(const void* ei, size_t idx) {
    return g_is64 ? (int)((const long long*)ei)[idx]
                  : ((const int*)ei)[idx];
}

// ---------------- kernel: degree histogram ----------------
__global__ void k_hist(const void* __restrict__ ei) {
    int e = blockIdx.x * blockDim.x + threadIdx.x;
    if (e >= N_EDGES) return;
    int d = edge_at(ei, (size_t)N_EDGES + e);
    atomicAdd(&g_deg[d], 1);
}

// ---------------- bf16 split-pack: float4 -> hi uint2 + lo uint2 ----------
__device__ __forceinline__ uint2 split_pack4(float4 v, uint2& lo_out) {
    float2 p0 = make_float2(v.x, v.y);
    float2 p1 = make_float2(v.z, v.w);
    __nv_bfloat162 h0 = __float22bfloat162_rn(p0);
    __nv_bfloat162 h1 = __float22bfloat162_rn(p1);
    float2 b0 = __bfloat1622float2(h0);
    float2 b1 = __bfloat1622float2(h1);
    __nv_bfloat162 l0 = __float22bfloat162_rn(make_float2(p0.x - b0.x, p0.y - b0.y));
    __nv_bfloat162 l1 = __float22bfloat162_rn(make_float2(p1.x - b1.x, p1.y - b1.y));
    lo_out = make_uint2(*(uint32_t*)&l0, *(uint32_t*)&l1);
    return make_uint2(*(uint32_t*)&h0, *(uint32_t*)&h1);
}

__device__ __forceinline__ void mma_bf16(float* d, const uint32_t* a,
                                         uint32_t b0, uint32_t b1) {
    asm volatile(
        "mma.sync.aligned.m16n8k16.row.col.f32.bf16.bf16.f32 "
        "{%0,%1,%2,%3}, {%4,%5,%6,%7}, {%8,%9}, {%0,%1,%2,%3};\n"
        : "+f"(d[0]), "+f"(d[1]), "+f"(d[2]), "+f"(d[3])
        : "r"(a[0]), "r"(a[1]), "r"(a[2]), "r"(a[3]), "r"(b0), "r"(b1));
}

__device__ __forceinline__ void ldsm_x4(uint32_t& r0, uint32_t& r1,
                                        uint32_t& r2, uint32_t& r3,
                                        uint32_t addr) {
    asm volatile("ldmatrix.sync.aligned.m8n8.x4.shared.b16 {%0,%1,%2,%3}, [%4];"
                 : "=r"(r0), "=r"(r1), "=r"(r2), "=r"(r3) : "r"(addr));
}

// ---------------- kernel: dual GEMM on tensor cores (bf16x3 + ldmatrix) ----
#define GBM 128
#define GBK 64
#define PADK 72
#define BUF_E (GBM * PADK)                                       // 9216 bf16
#define SMEM_GEMM (4 * BUF_E * (int)sizeof(__nv_bfloat16))       // 73728 bytes

__global__ __launch_bounds__(256, 2)
void k_gemm_tc(const float* __restrict__ X,
               const float* __restrict__ Wg,
               const float* __restrict__ Wf,
               const float* __restrict__ att_s,
               const float* __restrict__ att_d) {
    extern __shared__ __nv_bfloat16 smem[];
    __nv_bfloat16 (*Ahi)[PADK] = (__nv_bfloat16(*)[PADK])(smem);
    __nv_bfloat16 (*Alo)[PADK] = (__nv_bfloat16(*)[PADK])(smem + 1 * BUF_E);
    __nv_bfloat16 (*Bhi)[PADK] = (__nv_bfloat16(*)[PADK])(smem + 2 * BUF_E);
    __nv_bfloat16 (*Blo)[PADK] = (__nv_bfloat16(*)[PADK])(smem + 3 * BUF_E);
    const uint32_t sbase = (uint32_t)__cvta_generic_to_shared(smem);

    const int is_h = (blockIdx.y == 0);
    const float* W = is_h ? Wg : Wf;
    float* C = g_hx + (is_h ? 0 : OUT_DIM);        // interleaved, row stride 256

    const int row0 = blockIdx.x * GBM;
    const int tid  = threadIdx.x;
    const int warp = tid >> 5, lane = tid & 31;
    const int wm = warp & 3;
    const int wn = warp >> 2;
    const int gid = lane >> 2;
    const int tig = lane & 3;

    const int laneA_row = lane & 15;
    const int laneA_col = (lane >> 4) * 8;
    const int laneB_grp = (lane >> 4) * 8;
    const int laneB_row = lane & 7;
    const int laneB_col = ((lane >> 3) & 1) * 8;

    uint32_t aAhi[2], aAlo[2], aBhi[4], aBlo[4];
    #pragma unroll
    for (int mi = 0; mi < 2; mi++) {
        int r = wm * 32 + mi * 16 + laneA_row;
        aAhi[mi] = sbase + (uint32_t)((0 * BUF_E + r * PADK + laneA_col) * 2);
        aAlo[mi] = sbase + (uint32_t)((1 * BUF_E + r * PADK + laneA_col) * 2);
    }
    #pragma unroll
    for (int nh = 0; nh < 4; nh++) {
        int n = wn * 64 + nh * 16 + laneB_grp + laneB_row;
        aBhi[nh] = sbase + (uint32_t)((2 * BUF_E + n * PADK + laneB_col) * 2);
        aBlo[nh] = sbase + (uint32_t)((3 * BUF_E + n * PADK + laneB_col) * 2);
    }

    float acc[2][8][4];
    #pragma unroll
    for (int mi = 0; mi < 2; mi++)
        #pragma unroll
        for (int ni = 0; ni < 8; ni++)
            #pragma unroll
            for (int j = 0; j < 4; j++) acc[mi][ni][j] = 0.0f;

    for (int k0 = 0; k0 < IN_DIM; k0 += GBK) {
        #pragma unroll
        for (int i = 0; i < 8; i++) {
            int idx = tid + i * 256;
            int m   = idx >> 4;
            int k4  = (idx & 15) << 2;
            float4 v = make_float4(0.f, 0.f, 0.f, 0.f);
            if (row0 + m < N_NODES)
                v = *(const float4*)(X + (size_t)(row0 + m) * IN_DIM + k0 + k4);
            uint2 lo;
            uint2 hi = split_pack4(v, lo);
            *(uint2*)&Ahi[m][k4] = hi;
            *(uint2*)&Alo[m][k4] = lo;
        }
        #pragma unroll
        for (int i = 0; i < 8; i++) {
            int idx = tid + i * 256;
            int n   = idx >> 4;
            int k4  = (idx & 15) << 2;
            float4 v = *(const float4*)(W + (size_t)n * IN_DIM + k0 + k4);
            uint2 lo;
            uint2 hi = split_pack4(v, lo);
            *(uint2*)&Bhi[n][k4] = hi;
            *(uint2*)&Blo[n][k4] = lo;
        }
        __syncthreads();

        #pragma unroll
        for (int ks = 0; ks < 4; ks++) {
            const uint32_t koff = (uint32_t)(ks * 16 * 2);
            uint32_t ah[2][4], al[2][4];
            #pragma unroll
            for (int mi = 0; mi < 2; mi++) {
                ldsm_x4(ah[mi][0], ah[mi][1], ah[mi][2], ah[mi][3], aAhi[mi] + koff);
                ldsm_x4(al[mi][0], al[mi][1], al[mi][2], al[mi][3], aAlo[mi] + koff);
            }
            #pragma unroll
            for (int nh = 0; nh < 4; nh++) {
                uint32_t bh[4], bl[4];
                ldsm_x4(bh[0], bh[1], bh[2], bh[3], aBhi[nh] + koff);
                ldsm_x4(bl[0], bl[1], bl[2], bl[3], aBlo[nh] + koff);
                #pragma unroll
                for (int half = 0; half < 2; half++) {
                    int ni = nh * 2 + half;
                    uint32_t bh0 = bh[half * 2], bh1 = bh[half * 2 + 1];
                    uint32_t bl0 = bl[half * 2], bl1 = bl[half * 2 + 1];
                    #pragma unroll
                    for (int mi = 0; mi < 2; mi++) {
                        mma_bf16(acc[mi][ni], ah[mi], bh0, bh1);
                        mma_bf16(acc[mi][ni], al[mi], bh0, bh1);
                        mma_bf16(acc[mi][ni], ah[mi], bl0, bl1);
                    }
                }
            }
        }
        __syncthreads();
    }

    // ---- epilogue: store into interleaved g_hx (row stride 256) ----
    #pragma unroll
    for (int mi = 0; mi < 2; mi++) {
        #pragma unroll
        for (int ni = 0; ni < 8; ni++) {
            int col = wn * 64 + ni * 8 + 2 * tig;
            int r0  = row0 + wm * 32 + mi * 16 + gid;
            if (r0 < N_NODES)
                *(float2*)(C + (size_t)r0 * 2 * OUT_DIM + col) =
                    make_float2(acc[mi][ni][0], acc[mi][ni][1]);
            int r1 = r0 + 8;
            if (r1 < N_NODES)
                *(float2*)(C + (size_t)r1 * 2 * OUT_DIM + col) =
                    make_float2(acc[mi][ni][2], acc[mi][ni][3]);
        }
    }

    // ---- fused attention dots (h branch only) ----
    if (is_h) {
        #pragma unroll
        for (int mi = 0; mi < 2; mi++) {
            float s0 = 0.f, d0 = 0.f, s1 = 0.f, d1 = 0.f;
            #pragma unroll
            for (int ni = 0; ni < 8; ni++) {
                int col = wn * 64 + ni * 8 + 2 * tig;
                float a0 = __ldg(att_s + col), a1 = __ldg(att_s + col + 1);
                float b0 = __ldg(att_d + col), b1 = __ldg(att_d + col + 1);
                s0 += acc[mi][ni][0] * a0 + acc[mi][ni][1] * a1;
                d0 += acc[mi][ni][0] * b0 + acc[mi][ni][1] * b1;
                s1 += acc[mi][ni][2] * a0 + acc[mi][ni][3] * a1;
                d1 += acc[mi][ni][2] * b0 + acc[mi][ni][3] * b1;
            }
            #pragma unroll
            for (int o = 1; o <= 2; o <<= 1) {
                s0 += __shfl_xor_sync(0xffffffffu, s0, o);
                d0 += __shfl_xor_sync(0xffffffffu, d0, o);
                s1 += __shfl_xor_sync(0xffffffffu, s1, o);
                d1 += __shfl_xor_sync(0xffffffffu, d1, o);
            }
            if (tig == 0) {
                int r0 = row0 + wm * 32 + mi * 16 + gid;
                if (r0 < N_NODES) {
                    atomicAdd(&g_asrc[r0], s0);
                    atomicAdd(&g_adst[r0], d0);
                }
                int r1 = r0 + 8;
                if (r1 < N_NODES) {
                    atomicAdd(&g_asrc[r1], s1);
                    atomicAdd(&g_adst[r1], d1);
                }
            }
        }
    }
}

// ---------------- scan kernels ----------------
__global__ void k_scan1() {
    __shared__ int sh[SCAN_B];
    int i = blockIdx.x * SCAN_B + threadIdx.x;
    int v = (i < N_NODES) ? g_deg[i] : 0;
    sh[threadIdx.x] = v;
    __syncthreads();
    for (int o = 1; o < SCAN_B; o <<= 1) {
        int t = (threadIdx.x >= o) ? sh[threadIdx.x - o] : 0;
        __syncthreads();
        sh[threadIdx.x] += t;
        __syncthreads();
    }
    if (i < N_NODES) g_off[i] = sh[threadIdx.x] - v;
    if (threadIdx.x == SCAN_B - 1) g_bsum[blockIdx.x] = sh[threadIdx.x];
}

__global__ void k_scan2() {
    __shared__ int sh[128];
    int v = (threadIdx.x < NCHUNK) ? g_bsum[threadIdx.x] : 0;
    sh[threadIdx.x] = v;
    __syncthreads();
    for (int o = 1; o < 128; o <<= 1) {
        int t = (threadIdx.x >= o) ? sh[threadIdx.x - o] : 0;
        __syncthreads();
        sh[threadIdx.x] += t;
        __syncthreads();
    }
    if (threadIdx.x < NCHUNK) g_bsum[threadIdx.x] = sh[threadIdx.x] - v;
}

__global__ void k_scan3() {
    int i = blockIdx.x * SCAN_B + threadIdx.x;
    if (i < N_NODES) g_off[i] += g_bsum[blockIdx.x];
}

// ---------------- kernel: scatter edges into CSR ----------------
__global__ void k_scatter(const void* __restrict__ ei,
                          const float* __restrict__ beta) {
    int e = blockIdx.x * blockDim.x + threadIdx.x;
    if (e >= N_EDGES) return;
    int s = edge_at(ei, e);
    int d = edge_at(ei, (size_t)N_EDGES + e);
    int pos = g_off[d] + atomicAdd(&g_cursor[d], 1);
    g_csr_src[pos]  = s;
    g_csr_beta[pos] = beta[e];
}

// ---------------- kernel: warp-per-node fused aggregation ----------------
// Phase 2: lane-parallel coefficient computation + shfl broadcast, so the
// sigmoid/asrc chain runs once per edge instead of 32x.
__global__ __launch_bounds__(256)
void k_agg(const float* __restrict__ bias, float* __restrict__ out) {
    int node = (blockIdx.x * blockDim.x + threadIdx.x) >> 5;
    if (node >= N_NODES) return;
    int lane = threadIdx.x & 31;

    int beg = g_off[node];
    int deg = g_deg[node];
    int end = beg + deg;
    float adst = g_adst[node];

    // phase 1: denom via lane-parallel alpha + warp reduce
    float psum = 0.0f;
    for (int i = beg + lane; i < end; i += 32) {
        int s = g_csr_src[i];
        float xv = g_asrc[s] + adst;
        if (xv < 0.0f) xv *= NEG_SLOPE;
        psum += 1.0f / (1.0f + expf(-xv));
    }
    #pragma unroll
    for (int o = 16; o; o >>= 1) psum += __shfl_xor_sync(0xffffffffu, psum, o);
    float invden = LAMBDA / (psum + EPS_);

    // phase 2: chunked. Lane l computes coefs for edge base+l; then all lanes
    // process the chunk's edges via shfl broadcast doing only gathers + FMA.
    float4 acc = make_float4(0.f, 0.f, 0.f, 0.f);
    for (int base = beg; base < end; base += 32) {
        int i = base + lane;
        float cA = 0.0f, cB = 0.0f;
        int   sl = 0;
        if (i < end) {
            sl = g_csr_src[i];
            float xv = g_asrc[sl] + adst;
            if (xv < 0.0f) xv *= NEG_SLOPE;
            cA = invden / (1.0f + expf(-xv));
            cB = (1.0f - LAMBDA) * g_csr_beta[i];
        }
        int cnt = min(32, end - base);
        for (int j = 0; j < cnt; j++) {
            float a = __shfl_sync(0xffffffffu, cA, j);
            float b = __shfl_sync(0xffffffffu, cB, j);
            int   s = __shfl_sync(0xffffffffu, sl, j);
            const float4* hp = (const float4*)(g_hx + (size_t)s * 2 * OUT_DIM);
            float4 h4 = __ldg(hp + lane);
            float4 x4 = __ldg(hp + 32 + lane);
            acc.x += a * h4.x + b * x4.x;
            acc.y += a * h4.y + b * x4.y;
            acc.z += a * h4.z + b * x4.z;
            acc.w += a * h4.w + b * x4.w;
        }
    }

    // epilogue: + lam*bias, ELU, single store
    float4 bv = *(const float4*)(bias + lane * 4);
    float4 v;
    v.x = acc.x + LAMBDA * bv.x;
    v.y = acc.y + LAMBDA * bv.y;
    v.z = acc.z + LAMBDA * bv.z;
    v.w = acc.w + LAMBDA * bv.w;
    v.x = (v.x > 0.0f) ? v.x : expm1f(v.x);
    v.y = (v.y > 0.0f) ? v.y : expm1f(v.y);
    v.z = (v.z > 0.0f) ? v.z : expm1f(v.z);
    v.w = (v.w > 0.0f) ? v.w : expm1f(v.w);
    *(float4*)(out + (size_t)node * OUT_DIM + lane * 4) = v;
}

// ---------------- launch ----------------
extern "C" void kernel_launch(void* const* d_in, const int* in_sizes, int n_in,
                              void* d_out, int out_size) {
    const float* x       = (const float*)d_in[0];
    const void*  ei      = d_in[1];
    const float* beta    = (const float*)d_in[2];
    const float* W_gat   = (const float*)d_in[3];
    const float* att_src = (const float*)d_in[4];
    const float* att_dst = (const float*)d_in[5];
    const float* bias    = (const float*)d_in[6];
    const float* W_fixed = (const float*)d_in[7];
    float* out = (float*)d_out;

    static cudaStream_t s2 = nullptr;
    static cudaEvent_t evFork = nullptr, evJoin = nullptr;
    static int init_done = 0;
    if (!init_done) {
        cudaFuncSetAttribute(k_gemm_tc,
                             cudaFuncAttributeMaxDynamicSharedMemorySize,
                             SMEM_GEMM);
        cudaStreamCreateWithFlags(&s2, cudaStreamNonBlocking);
        cudaEventCreateWithFlags(&evFork, cudaEventDisableTiming);
        cudaEventCreateWithFlags(&evJoin, cudaEventDisableTiming);
        init_done = 1;
    }

    // prologue on main stream: zero scratch used by both branches
    k_zero_misc<<<(N_NODES + 255) / 256, 256>>>();

    // ---- fork: CSR build on s2, GEMM on main ----
    cudaEventRecord(evFork, 0);
    cudaStreamWaitEvent(s2, evFork, 0);

    {   // dual GEMM + fused attention dots (main stream)
        dim3 grid((N_NODES + GBM - 1) / GBM, 2);
        k_gemm_tc<<<grid, 256, SMEM_GEMM>>>(x, W_gat, W_fixed, att_src, att_dst);
    }

    // side stream: CSR build
    k_sniff<<<1, 32, 0, s2>>>((const int*)ei);
    k_hist<<<(N_EDGES + 255) / 256, 256, 0, s2>>>(ei);
    k_scan1<<<NCHUNK, SCAN_B, 0, s2>>>();
    k_scan2<<<1, 128, 0, s2>>>();
    k_scan3<<<NCHUNK, SCAN_B, 0, s2>>>();
    k_scatter<<<(N_EDGES + 255) / 256, 256, 0, s2>>>(ei, beta);

    // ---- join ----
    cudaEventRecord(evJoin, s2);
    cudaStreamWaitEvent(0, evJoin, 0);

    // fused aggregation + bias + ELU
    k_agg<<<(N_NODES * 32 + 255) / 256, 256>>>(bias, out);
}

// round 11
// speedup vs baseline: 1.4717x; 1.2317x over previous
#include <cuda_runtime.h>
#include <cuda_bf16.h>
#include <cuda_fp16.h>
#include <math.h>
#include <stdint.h>

// ---------------- problem constants ----------------
#define N_NODES   100000
#define N_EDGES   1600000
#define IN_DIM    256
#define OUT_DIM   128
#define NEG_SLOPE 0.2f
#define LAMBDA    0.5f
#define EPS_      1e-8f

// ---------------- device scratch (static, no allocs) ----------------
// g_hx: interleaved fp16 [node][0:128)=h, [128:256)=xw  (512B per node)
__device__ __half g_hx[(size_t)N_NODES * 2 * OUT_DIM];
__device__ float g_asrc[N_NODES];
__device__ float g_adst[N_NODES];
__device__ int   g_deg[N_NODES];
__device__ int   g_off[N_NODES];
__device__ int   g_cursor[N_NODES];
__device__ int   g_csr_src[N_EDGES];
__device__ float g_csr_beta[N_EDGES];
__device__ int   g_is64;

#define SCAN_B 1024
#define NCHUNK ((N_NODES + SCAN_B - 1) / SCAN_B)   // 98
__device__ int g_bsum[NCHUNK];

// ---------------- kernel 0: sniff edge_index dtype ----------------
__global__ void k_sniff(const int* __restrict__ ei_words) {
    if (threadIdx.x == 0 && blockIdx.x == 0) {
        int allzero = 1;
        #pragma unroll 1
        for (int i = 0; i < 64; i++) {
            if (ei_words[2 * i + 1] != 0) { allzero = 0; break; }
        }
        g_is64 = allzero;
    }
}

// ---------------- kernel 1: zero small scratch ----------------
__global__ void k_zero_misc() {
    int i = blockIdx.x * blockDim.x + threadIdx.x;
    if (i < N_NODES) {
        g_deg[i] = 0;
        g_cursor[i] = 0;
        g_asrc[i] = 0.0f;
        g_adst[i] = 0.0f;
    }
}

// ---------------- edge decode helpers ----------------
__device__ __forceinline__ int edge_at(const void* ei, size_t idx) {
    return g_is64 ? (int)((const long long*)ei)[idx]
                  : ((const int*)ei)[idx];
}

// ---------------- kernel: degree histogram ----------------
__global__ void k_hist(const void* __restrict__ ei) {
    int e = blockIdx.x * blockDim.x + threadIdx.x;
    if (e >= N_EDGES) return;
    int d = edge_at(ei, (size_t)N_EDGES + e);
    atomicAdd(&g_deg[d], 1);
}

// ---------------- bf16 split-pack: float4 -> hi uint2 + lo uint2 ----------
__device__ __forceinline__ uint2 split_pack4(float4 v, uint2& lo_out) {
    float2 p0 = make_float2(v.x, v.y);
    float2 p1 = make_float2(v.z, v.w);
    __nv_bfloat162 h0 = __float22bfloat162_rn(p0);
    __nv_bfloat162 h1 = __float22bfloat162_rn(p1);
    float2 b0 = __bfloat1622float2(h0);
    float2 b1 = __bfloat1622float2(h1);
    __nv_bfloat162 l0 = __float22bfloat162_rn(make_float2(p0.x - b0.x, p0.y - b0.y));
    __nv_bfloat162 l1 = __float22bfloat162_rn(make_float2(p1.x - b1.x, p1.y - b1.y));
    lo_out = make_uint2(*(uint32_t*)&l0, *(uint32_t*)&l1);
    return make_uint2(*(uint32_t*)&h0, *(uint32_t*)&h1);
}

__device__ __forceinline__ void mma_bf16(float* d, const uint32_t* a,
                                         uint32_t b0, uint32_t b1) {
    asm volatile(
        "mma.sync.aligned.m16n8k16.row.col.f32.bf16.bf16.f32 "
        "{%0,%1,%2,%3}, {%4,%5,%6,%7}, {%8,%9}, {%0,%1,%2,%3};\n"
        : "+f"(d[0]), "+f"(d[1]), "+f"(d[2]), "+f"(d[3])
        : "r"(a[0]), "r"(a[1]), "r"(a[2]), "r"(a[3]), "r"(b0), "r"(b1));
}

__device__ __forceinline__ void ldsm_x4(uint32_t& r0, uint32_t& r1,
                                        uint32_t& r2, uint32_t& r3,
                                        uint32_t addr) {
    asm volatile("ldmatrix.sync.aligned.m8n8.x4.shared.b16 {%0,%1,%2,%3}, [%4];"
                 : "=r"(r0), "=r"(r1), "=r"(r2), "=r"(r3) : "r"(addr));
}

// ---------------- kernel: dual GEMM on tensor cores (bf16x3 + ldmatrix) ----
#define GBM 128
#define GBK 64
#define PADK 72
#define BUF_E (GBM * PADK)                                       // 9216 bf16
#define SMEM_GEMM (4 * BUF_E * (int)sizeof(__nv_bfloat16))       // 73728 bytes

__global__ __launch_bounds__(256, 2)
void k_gemm_tc(const float* __restrict__ X,
               const float* __restrict__ Wg,
               const float* __restrict__ Wf,
               const float* __restrict__ att_s,
               const float* __restrict__ att_d) {
    extern __shared__ __nv_bfloat16 smem[];
    __nv_bfloat16 (*Ahi)[PADK] = (__nv_bfloat16(*)[PADK])(smem);
    __nv_bfloat16 (*Alo)[PADK] = (__nv_bfloat16(*)[PADK])(smem + 1 * BUF_E);
    __nv_bfloat16 (*Bhi)[PADK] = (__nv_bfloat16(*)[PADK])(smem + 2 * BUF_E);
    __nv_bfloat16 (*Blo)[PADK] = (__nv_bfloat16(*)[PADK])(smem + 3 * BUF_E);
    const uint32_t sbase = (uint32_t)__cvta_generic_to_shared(smem);

    const int is_h = (blockIdx.y == 0);
    const float* W = is_h ? Wg : Wf;
    __half* C = g_hx + (is_h ? 0 : OUT_DIM);       // interleaved, row stride 256

    const int row0 = blockIdx.x * GBM;
    const int tid  = threadIdx.x;
    const int warp = tid >> 5, lane = tid & 31;
    const int wm = warp & 3;
    const int wn = warp >> 2;
    const int gid = lane >> 2;
    const int tig = lane & 3;

    const int laneA_row = lane & 15;
    const int laneA_col = (lane >> 4) * 8;
    const int laneB_grp = (lane >> 4) * 8;
    const int laneB_row = lane & 7;
    const int laneB_col = ((lane >> 3) & 1) * 8;

    uint32_t aAhi[2], aAlo[2], aBhi[4], aBlo[4];
    #pragma unroll
    for (int mi = 0; mi < 2; mi++) {
        int r = wm * 32 + mi * 16 + laneA_row;
        aAhi[mi] = sbase + (uint32_t)((0 * BUF_E + r * PADK + laneA_col) * 2);
        aAlo[mi] = sbase + (uint32_t)((1 * BUF_E + r * PADK + laneA_col) * 2);
    }
    #pragma unroll
    for (int nh = 0; nh < 4; nh++) {
        int n = wn * 64 + nh * 16 + laneB_grp + laneB_row;
        aBhi[nh] = sbase + (uint32_t)((2 * BUF_E + n * PADK + laneB_col) * 2);
        aBlo[nh] = sbase + (uint32_t)((3 * BUF_E + n * PADK + laneB_col) * 2);
    }

    float acc[2][8][4];
    #pragma unroll
    for (int mi = 0; mi < 2; mi++)
        #pragma unroll
        for (int ni = 0; ni < 8; ni++)
            #pragma unroll
            for (int j = 0; j < 4; j++) acc[mi][ni][j] = 0.0f;

    for (int k0 = 0; k0 < IN_DIM; k0 += GBK) {
        #pragma unroll
        for (int i = 0; i < 8; i++) {
            int idx = tid + i * 256;
            int m   = idx >> 4;
            int k4  = (idx & 15) << 2;
            float4 v = make_float4(0.f, 0.f, 0.f, 0.f);
            if (row0 + m < N_NODES)
                v = *(const float4*)(X + (size_t)(row0 + m) * IN_DIM + k0 + k4);
            uint2 lo;
            uint2 hi = split_pack4(v, lo);
            *(uint2*)&Ahi[m][k4] = hi;
            *(uint2*)&Alo[m][k4] = lo;
        }
        #pragma unroll
        for (int i = 0; i < 8; i++) {
            int idx = tid + i * 256;
            int n   = idx >> 4;
            int k4  = (idx & 15) << 2;
            float4 v = *(const float4*)(W + (size_t)n * IN_DIM + k0 + k4);
            uint2 lo;
            uint2 hi = split_pack4(v, lo);
            *(uint2*)&Bhi[n][k4] = hi;
            *(uint2*)&Blo[n][k4] = lo;
        }
        __syncthreads();

        #pragma unroll
        for (int ks = 0; ks < 4; ks++) {
            const uint32_t koff = (uint32_t)(ks * 16 * 2);
            uint32_t ah[2][4], al[2][4];
            #pragma unroll
            for (int mi = 0; mi < 2; mi++) {
                ldsm_x4(ah[mi][0], ah[mi][1], ah[mi][2], ah[mi][3], aAhi[mi] + koff);
                ldsm_x4(al[mi][0], al[mi][1], al[mi][2], al[mi][3], aAlo[mi] + koff);
            }
            #pragma unroll
            for (int nh = 0; nh < 4; nh++) {
                uint32_t bh[4], bl[4];
                ldsm_x4(bh[0], bh[1], bh[2], bh[3], aBhi[nh] + koff);
                ldsm_x4(bl[0], bl[1], bl[2], bl[3], aBlo[nh] + koff);
                #pragma unroll
                for (int half = 0; half < 2; half++) {
                    int ni = nh * 2 + half;
                    uint32_t bh0 = bh[half * 2], bh1 = bh[half * 2 + 1];
                    uint32_t bl0 = bl[half * 2], bl1 = bl[half * 2 + 1];
                    #pragma unroll
                    for (int mi = 0; mi < 2; mi++) {
                        mma_bf16(acc[mi][ni], ah[mi], bh0, bh1);
                        mma_bf16(acc[mi][ni], al[mi], bh0, bh1);
                        mma_bf16(acc[mi][ni], ah[mi], bl0, bl1);
                    }
                }
            }
        }
        __syncthreads();
    }

    // ---- epilogue: store fp16 into interleaved g_hx (row stride 256) ----
    #pragma unroll
    for (int mi = 0; mi < 2; mi++) {
        #pragma unroll
        for (int ni = 0; ni < 8; ni++) {
            int col = wn * 64 + ni * 8 + 2 * tig;
            int r0  = row0 + wm * 32 + mi * 16 + gid;
            if (r0 < N_NODES)
                *(__half2*)(C + (size_t)r0 * 2 * OUT_DIM + col) =
                    __floats2half2_rn(acc[mi][ni][0], acc[mi][ni][1]);
            int r1 = r0 + 8;
            if (r1 < N_NODES)
                *(__half2*)(C + (size_t)r1 * 2 * OUT_DIM + col) =
                    __floats2half2_rn(acc[mi][ni][2], acc[mi][ni][3]);
        }
    }

    // ---- fused attention dots (h branch only, fp32 accumulators) ----
    if (is_h) {
        #pragma unroll
        for (int mi = 0; mi < 2; mi++) {
            float s0 = 0.f, d0 = 0.f, s1 = 0.f, d1 = 0.f;
            #pragma unroll
            for (int ni = 0; ni < 8; ni++) {
                int col = wn * 64 + ni * 8 + 2 * tig;
                float a0 = __ldg(att_s + col), a1 = __ldg(att_s + col + 1);
                float b0 = __ldg(att_d + col), b1 = __ldg(att_d + col + 1);
                s0 += acc[mi][ni][0] * a0 + acc[mi][ni][1] * a1;
                d0 += acc[mi][ni][0] * b0 + acc[mi][ni][1] * b1;
                s1 += acc[mi][ni][2] * a0 + acc[mi][ni][3] * a1;
                d1 += acc[mi][ni][2] * b0 + acc[mi][ni][3] * b1;
            }
            #pragma unroll
            for (int o = 1; o <= 2; o <<= 1) {
                s0 += __shfl_xor_sync(0xffffffffu, s0, o);
                d0 += __shfl_xor_sync(0xffffffffu, d0, o);
                s1 += __shfl_xor_sync(0xffffffffu, s1, o);
                d1 += __shfl_xor_sync(0xffffffffu, d1, o);
            }
            if (tig == 0) {
                int r0 = row0 + wm * 32 + mi * 16 + gid;
                if (r0 < N_NODES) {
                    atomicAdd(&g_asrc[r0], s0);
                    atomicAdd(&g_adst[r0], d0);
                }
                int r1 = r0 + 8;
                if (r1 < N_NODES) {
                    atomicAdd(&g_asrc[r1], s1);
                    atomicAdd(&g_adst[r1], d1);
                }
            }
        }
    }
}

// ---------------- scan kernels ----------------
__global__ void k_scan1() {
    __shared__ int sh[SCAN_B];
    int i = blockIdx.x * SCAN_B + threadIdx.x;
    int v = (i < N_NODES) ? g_deg[i] : 0;
    sh[threadIdx.x] = v;
    __syncthreads();
    for (int o = 1; o < SCAN_B; o <<= 1) {
        int t = (threadIdx.x >= o) ? sh[threadIdx.x - o] : 0;
        __syncthreads();
        sh[threadIdx.x] += t;
        __syncthreads();
    }
    if (i < N_NODES) g_off[i] = sh[threadIdx.x] - v;
    if (threadIdx.x == SCAN_B - 1) g_bsum[blockIdx.x] = sh[threadIdx.x];
}

__global__ void k_scan2() {
    __shared__ int sh[128];
    int v = (threadIdx.x < NCHUNK) ? g_bsum[threadIdx.x] : 0;
    sh[threadIdx.x] = v;
    __syncthreads();
    for (int o = 1; o < 128; o <<= 1) {
        int t = (threadIdx.x >= o) ? sh[threadIdx.x - o] : 0;
        __syncthreads();
        sh[threadIdx.x] += t;
        __syncthreads();
    }
    if (threadIdx.x < NCHUNK) g_bsum[threadIdx.x] = sh[threadIdx.x] - v;
}

__global__ void k_scan3() {
    int i = blockIdx.x * SCAN_B + threadIdx.x;
    if (i < N_NODES) g_off[i] += g_bsum[blockIdx.x];
}

// ---------------- kernel: scatter edges into CSR ----------------
__global__ void k_scatter(const void* __restrict__ ei,
                          const float* __restrict__ beta) {
    int e = blockIdx.x * blockDim.x + threadIdx.x;
    if (e >= N_EDGES) return;
    int s = edge_at(ei, e);
    int d = edge_at(ei, (size_t)N_EDGES + e);
    int pos = g_off[d] + atomicAdd(&g_cursor[d], 1);
    g_csr_src[pos]  = s;
    g_csr_beta[pos] = beta[e];
}

// ---------------- kernel: warp-per-node fused aggregation (fp16 gathers) ---
__global__ __launch_bounds__(256)
void k_agg(const float* __restrict__ bias, float* __restrict__ out) {
    int node = (blockIdx.x * blockDim.x + threadIdx.x) >> 5;
    if (node >= N_NODES) return;
    int lane = threadIdx.x & 31;

    int beg = g_off[node];
    int deg = g_deg[node];
    int end = beg + deg;
    float adst = g_adst[node];

    // phase 1: denom via lane-parallel alpha + warp reduce (fp32)
    float psum = 0.0f;
    for (int i = beg + lane; i < end; i += 32) {
        int s = g_csr_src[i];
        float xv = g_asrc[s] + adst;
        if (xv < 0.0f) xv *= NEG_SLOPE;
        psum += 1.0f / (1.0f + expf(-xv));
    }
    #pragma unroll
    for (int o = 16; o; o >>= 1) psum += __shfl_xor_sync(0xffffffffu, psum, o);
    float invden = LAMBDA / (psum + EPS_);

    // phase 2: chunked; lane-parallel coefs + shfl broadcast; fp16 gathers
    float4 acc = make_float4(0.f, 0.f, 0.f, 0.f);
    for (int base = beg; base < end; base += 32) {
        int i = base + lane;
        float cA = 0.0f, cB = 0.0f;
        int   sl = 0;
        if (i < end) {
            sl = g_csr_src[i];
            float xv = g_asrc[sl] + adst;
            if (xv < 0.0f) xv *= NEG_SLOPE;
            cA = invden / (1.0f + expf(-xv));
            cB = (1.0f - LAMBDA) * g_csr_beta[i];
        }
        int cnt = min(32, end - base);
        for (int j = 0; j < cnt; j++) {
            float a = __shfl_sync(0xffffffffu, cA, j);
            float b = __shfl_sync(0xffffffffu, cB, j);
            int   s = __shfl_sync(0xffffffffu, sl, j);
            const uint2* hp = (const uint2*)(g_hx + (size_t)s * 2 * OUT_DIM);
            uint2 hraw = __ldg(hp + lane);          // 4 fp16 of h
            uint2 xraw = __ldg(hp + 32 + lane);     // 4 fp16 of xw
            float2 h0 = __half22float2(*(__half2*)&hraw.x);
            float2 h1 = __half22float2(*(__half2*)&hraw.y);
            float2 x0 = __half22float2(*(__half2*)&xraw.x);
            float2 x1 = __half22float2(*(__half2*)&xraw.y);
            acc.x += a * h0.x + b * x0.x;
            acc.y += a * h0.y + b * x0.y;
            acc.z += a * h1.x + b * x1.x;
            acc.w += a * h1.y + b * x1.y;
        }
    }

    // epilogue: + lam*bias, ELU, single store (fp32 out)
    float4 bv = *(const float4*)(bias + lane * 4);
    float4 v;
    v.x = acc.x + LAMBDA * bv.x;
    v.y = acc.y + LAMBDA * bv.y;
    v.z = acc.z + LAMBDA * bv.z;
    v.w = acc.w + LAMBDA * bv.w;
    v.x = (v.x > 0.0f) ? v.x : expm1f(v.x);
    v.y = (v.y > 0.0f) ? v.y : expm1f(v.y);
    v.z = (v.z > 0.0f) ? v.z : expm1f(v.z);
    v.w = (v.w > 0.0f) ? v.w : expm1f(v.w);
    *(float4*)(out + (size_t)node * OUT_DIM + lane * 4) = v;
}

// ---------------- launch ----------------
extern "C" void kernel_launch(void* const* d_in, const int* in_sizes, int n_in,
                              void* d_out, int out_size) {
    const float* x       = (const float*)d_in[0];
    const void*  ei      = d_in[1];
    const float* beta    = (const float*)d_in[2];
    const float* W_gat   = (const float*)d_in[3];
    const float* att_src = (const float*)d_in[4];
    const float* att_dst = (const float*)d_in[5];
    const float* bias    = (const float*)d_in[6];
    const float* W_fixed = (const float*)d_in[7];
    float* out = (float*)d_out;

    static cudaStream_t s2 = nullptr;
    static cudaEvent_t evFork = nullptr, evJoin = nullptr;
    static int init_done = 0;
    if (!init_done) {
        cudaFuncSetAttribute(k_gemm_tc,
                             cudaFuncAttributeMaxDynamicSharedMemorySize,
                             SMEM_GEMM);
        cudaStreamCreateWithFlags(&s2, cudaStreamNonBlocking);
        cudaEventCreateWithFlags(&evFork, cudaEventDisableTiming);
        cudaEventCreateWithFlags(&evJoin, cudaEventDisableTiming);
        init_done = 1;
    }

    // prologue on main stream: zero scratch used by both branches
    k_zero_misc<<<(N_NODES + 255) / 256, 256>>>();

    // ---- fork: CSR build on s2, GEMM on main ----
    cudaEventRecord(evFork, 0);
    cudaStreamWaitEvent(s2, evFork, 0);

    {   // dual GEMM + fused attention dots (main stream)
        dim3 grid((N_NODES + GBM - 1) / GBM, 2);
        k_gemm_tc<<<grid, 256, SMEM_GEMM>>>(x, W_gat, W_fixed, att_src, att_dst);
    }

    // side stream: CSR build
    k_sniff<<<1, 32, 0, s2>>>((const int*)ei);
    k_hist<<<(N_EDGES + 255) / 256, 256, 0, s2>>>(ei);
    k_scan1<<<NCHUNK, SCAN_B, 0, s2>>>();
    k_scan2<<<1, 128, 0, s2>>>();
    k_scan3<<<NCHUNK, SCAN_B, 0, s2>>>();
    k_scatter<<<(N_EDGES + 255) / 256, 256, 0, s2>>>(ei, beta);

    // ---- join ----
    cudaEventRecord(evJoin, s2);
    cudaStreamWaitEvent(0, evJoin, 0);

    // fused aggregation + bias + ELU
    k_agg<<<(N_NODES * 32 + 255) / 256, 256>>>(bias, out);
}